// round 3
// baseline (speedup 1.0000x reference)
#include <cuda_runtime.h>
#include <cuda_bf16.h>
#include <cstdint>

// ---------------------------------------------------------------------------
// CopyBackProjection: 6 chained sparse 3x3x3 convolutions on a shared
// neighbor map.
//   1. Compact (mask, nbr) once per launch into CSR entries (k<<20 | src);
//      ~6% grid occupancy -> avg ~2.55 valid taps / voxel (90% of reference
//      FLOPs are masked zeros).
//   2. Fold tile(x,4) into Wd0 -> conv1 has Cin=8; "upsampled + r" becomes
//      x[n][co&7] added in conv6's epilogue.
//   3. bf16 everywhere on the residual path (error budget ~60x margin);
//      [N,32] bf16 buffer = 64MB, mostly L2-resident.
//   4. All conv weights staged in SMEM as bf16x2 ci-pairs; math is HFMA2
//      (halves both SMEM crossbar bytes and FMA instructions vs f32).
//   5. Gathered activation rows read via uniform LDG into registers (no
//      __syncwarp staging).  Mask dtype (bool) probed at runtime.
// ---------------------------------------------------------------------------

#define N_MAX (1 << 20)
#define KK 27

typedef unsigned int u32;

// Scratch (static device globals; no runtime allocation allowed)
__device__ int g_entries[KK * N_MAX];
__device__ int g_meta[N_MAX];  // (off<<5)|cnt
__device__ int g_blockSums[4096];
__device__ int g_maskIsByte;
__device__ float g_W1[KK * 8 * 32];  // folded Wd0
__device__ __align__(16) __nv_bfloat16 g_buf32[(size_t)N_MAX * 32];  // 64 MB
__device__ __align__(16) __nv_bfloat16 g_buf8a[(size_t)N_MAX * 8];   // 16 MB
__device__ __align__(16) __nv_bfloat16 g_buf8b[(size_t)N_MAX * 8];   // 16 MB

__device__ __forceinline__ __nv_bfloat162 bf2(u32 u) {
    __nv_bfloat162 h;
    *reinterpret_cast<u32*>(&h) = u;
    return h;
}
__device__ __forceinline__ u32 pk(float a, float b) {
    __nv_bfloat162 h = __floats2bfloat162_rn(a, b);
    return *reinterpret_cast<u32*>(&h);
}
__device__ __forceinline__ float sum2(__nv_bfloat162 a) {
    float2 f = __bfloat1622float2(a);
    return f.x + f.y;
}
__device__ __forceinline__ int maskAt(const void* m, size_t idx) {
    return g_maskIsByte ? (((const unsigned char*)m)[idx] != 0)
                        : (((const u32*)m)[idx] != 0u);
}

// ---------------------------------------------------------------------------
// Mask dtype probe.  bool-as-u8: nonzero bytes at both 4-aligned and
// non-aligned offsets.  bool-as-int32: nonzero only 4-aligned.  bool-as-f32
// (1.0f = 00 00 80 3F): nonzero only at offsets 4i+2 / 4i+3.
// ---------------------------------------------------------------------------
__global__ void probe_mask_kernel(const unsigned char* __restrict__ m) {
    __shared__ int sAligned, sUnaligned;
    if (threadIdx.x == 0) { sAligned = 0; sUnaligned = 0; }
    __syncthreads();
    int a = 0, u = 0;
    for (int i = threadIdx.x; i < 4096; i += 256) {
        if (m[i] != 0) {
            if ((i & 3) == 0) a = 1;
            else u = 1;
        }
    }
    if (a) atomicOr(&sAligned, 1);
    if (u) atomicOr(&sUnaligned, 1);
    __syncthreads();
    if (threadIdx.x == 0) g_maskIsByte = (sAligned && sUnaligned) ? 1 : 0;
}

// ---------------------------------------------------------------------------
// Compaction: count -> scan -> fill
// ---------------------------------------------------------------------------

__global__ void count_kernel(const void* __restrict__ mask, int N) {
    int tid = threadIdx.x;
    int n = blockIdx.x * 256 + tid;
    int cnt = 0;
    if (n < N) {
        size_t NN = (size_t)N;
#pragma unroll
        for (int k = 0; k < KK; k++) cnt += maskAt(mask, (size_t)k * NN + n);
        g_meta[n] = cnt;
    }
    int s = cnt;
#pragma unroll
    for (int o = 16; o > 0; o >>= 1) s += __shfl_down_sync(0xffffffffu, s, o);
    __shared__ int ws[8];
    if ((tid & 31) == 0) ws[tid >> 5] = s;
    __syncthreads();
    if (tid == 0) {
        int tot = 0;
#pragma unroll
        for (int i = 0; i < 8; i++) tot += ws[i];
        g_blockSums[blockIdx.x] = tot;
    }
}

__global__ void scan_blocks_kernel(int nb) {
    int tid = threadIdx.x;
    int base = tid * 4;
    int v[4];
#pragma unroll
    for (int i = 0; i < 4; i++) v[i] = (base + i < nb) ? g_blockSums[base + i] : 0;
    int tsum = v[0] + v[1] + v[2] + v[3];
    int lane = tid & 31, wid = tid >> 5;
    int x = tsum;
#pragma unroll
    for (int o = 1; o < 32; o <<= 1) {
        int y = __shfl_up_sync(0xffffffffu, x, o);
        if (lane >= o) x += y;
    }
    __shared__ int ws[32];
    __shared__ int wsx[32];
    if (lane == 31) ws[wid] = x;
    __syncthreads();
    if (tid < 32) {
        int vv = ws[tid];
        int xx = vv;
#pragma unroll
        for (int o = 1; o < 32; o <<= 1) {
            int y = __shfl_up_sync(0xffffffffu, xx, o);
            if (tid >= o) xx += y;
        }
        wsx[tid] = xx - vv;
    }
    __syncthreads();
    int run = wsx[wid] + (x - tsum);
#pragma unroll
    for (int i = 0; i < 4; i++) {
        int old = v[i];
        if (base + i < nb) g_blockSums[base + i] = run;
        run += old;
    }
}

__global__ void fill_kernel(const void* __restrict__ mask,
                            const int* __restrict__ nbr, int N) {
    int tid = threadIdx.x;
    int n = blockIdx.x * 256 + tid;
    int cnt = (n < N) ? (g_meta[n]) : 0;
    int lane = tid & 31, wid = tid >> 5;
    int x = cnt;
#pragma unroll
    for (int o = 1; o < 32; o <<= 1) {
        int y = __shfl_up_sync(0xffffffffu, x, o);
        if (lane >= o) x += y;
    }
    __shared__ int ws[8];
    __shared__ int wsx[8];
    if (lane == 31) ws[wid] = x;
    __syncthreads();
    if (tid < 8) {
        int vv = ws[tid];
        int xx = vv;
#pragma unroll
        for (int o = 1; o < 8; o <<= 1) {
            int y = __shfl_up_sync(0x000000ffu, xx, o);
            if (tid >= o) xx += y;
        }
        wsx[tid] = xx - vv;
    }
    __syncthreads();
    int off = g_blockSums[blockIdx.x] + wsx[wid] + (x - cnt);
    if (n < N) {
        g_meta[n] = (off << 5) | cnt;
        int w = off;
        size_t NN = (size_t)N;
#pragma unroll
        for (int k = 0; k < KK; k++) {
            if (maskAt(mask, (size_t)k * NN + n)) {
                g_entries[w++] = (k << 20) | nbr[(size_t)k * NN + n];
            }
        }
    }
}

// Fold tile(x,4) into Wd0: W1[k][ci][co] = sum_t Wd0[k][ci+8t][co]
__global__ void fold_kernel(const float* __restrict__ Wd0) {
    int i = blockIdx.x * 256 + threadIdx.x;
    if (i >= KK * 8 * 32) return;
    int co = i & 31;
    int ci = (i >> 5) & 7;
    int k = i >> 8;
    const float* base = Wd0 + (size_t)k * 1024 + co;
    g_W1[i] = base[ci * 32] + base[(ci + 8) * 32] + base[(ci + 16) * 32] +
              base[(ci + 24) * 32];
}

// ---------------------------------------------------------------------------
// Conv kernels.  Persistent grid-stride, warp-per-voxel.  Weights in SMEM as
// bf16x2 ci-pairs; activations gathered by uniform LDG into registers.
// ---------------------------------------------------------------------------

// conv1: x(f32,[N,8]) @ W1[27,8,32] -> g_buf32 (bf16).  lane = co.
// Wsh[k*64 + jp*32 + lane]: .x = pack(W[4jp+0][co], W[4jp+1][co]),
//                           .y = pack(W[4jp+2][co], W[4jp+3][co])
__global__ void __launch_bounds__(256) convA_kernel(const float* __restrict__ x, int N) {
    __shared__ uint2 Wsh[KK * 64];
    for (int t = threadIdx.x; t < KK * 64; t += 256) {
        int lane = t & 31, jp = (t >> 5) & 1, k = t >> 6;
        const float* wb = g_W1 + (k << 8) + lane;
        int c = jp * 4;
        uint2 u;
        u.x = pk(wb[c * 32], wb[(c + 1) * 32]);
        u.y = pk(wb[(c + 2) * 32], wb[(c + 3) * 32]);
        Wsh[t] = u;
    }
    __syncthreads();
    int lane = threadIdx.x & 31;
    int nwarp = gridDim.x * 8;
    for (int vox = blockIdx.x * 8 + (threadIdx.x >> 5); vox < N; vox += nwarp) {
        int m = g_meta[vox];
        int cnt = m & 31, off = m >> 5;
        __nv_bfloat162 acc0 = bf2(0u), acc1 = bf2(0u);
        for (int j = 0; j < cnt; ++j) {
            int e = __ldg(g_entries + off + j);
            int k = e >> 20, s = e & 0xFFFFF;
            const float4* p = reinterpret_cast<const float4*>(x + ((size_t)s << 3));
            float4 a = __ldg(p), b = __ldg(p + 1);
            u32 v0 = pk(a.x, a.y), v1 = pk(a.z, a.w);
            u32 v2 = pk(b.x, b.y), v3 = pk(b.z, b.w);
            const uint2* wk = Wsh + (k << 6) + lane;
            uint2 w0 = wk[0], w1 = wk[32];
            acc0 = __hfma2(bf2(v0), bf2(w0.x), acc0);
            acc1 = __hfma2(bf2(v1), bf2(w0.y), acc1);
            acc0 = __hfma2(bf2(v2), bf2(w1.x), acc0);
            acc1 = __hfma2(bf2(v3), bf2(w1.y), acc1);
        }
        g_buf32[((size_t)vox << 5) + lane] =
            __float2bfloat16(sum2(acc0) + sum2(acc1));
    }
}

// conv2: g_buf32(bf16,[N,32]) @ Wd1[27,32,8] -> g_buf8a.  co=lane&7, g=lane>>3
// covers ci in [8g,8g+8).  Wd1 layout [k][ci][co8].
__global__ void __launch_bounds__(256) convB_kernel(const float* __restrict__ W, int N) {
    __shared__ uint2 Wsh[KK * 64];
    for (int t = threadIdx.x; t < KK * 64; t += 256) {
        int lane = t & 31, jp = (t >> 5) & 1, k = t >> 6;
        int g = lane >> 3, co = lane & 7;
        const float* wb = W + (size_t)k * 256 + co;
        int c = g * 8 + jp * 4;
        uint2 u;
        u.x = pk(wb[c * 8], wb[(c + 1) * 8]);
        u.y = pk(wb[(c + 2) * 8], wb[(c + 3) * 8]);
        Wsh[t] = u;
    }
    __syncthreads();
    int lane = threadIdx.x & 31;
    int g = lane >> 3, co = lane & 7;
    int nwarp = gridDim.x * 8;
    for (int vox = blockIdx.x * 8 + (threadIdx.x >> 5); vox < N; vox += nwarp) {
        int m = g_meta[vox];
        int cnt = m & 31, off = m >> 5;
        __nv_bfloat162 acc0 = bf2(0u), acc1 = bf2(0u);
        for (int j = 0; j < cnt; ++j) {
            int e = __ldg(g_entries + off + j);
            int k = e >> 20, s = e & 0xFFFFF;
            const uint4* p =
                reinterpret_cast<const uint4*>(g_buf32 + ((size_t)s << 5) + (g << 3));
            uint4 q = __ldg(p);
            const uint2* wk = Wsh + (k << 6) + lane;
            uint2 w0 = wk[0], w1 = wk[32];
            acc0 = __hfma2(bf2(q.x), bf2(w0.x), acc0);
            acc1 = __hfma2(bf2(q.y), bf2(w0.y), acc1);
            acc0 = __hfma2(bf2(q.z), bf2(w1.x), acc0);
            acc1 = __hfma2(bf2(q.w), bf2(w1.y), acc1);
        }
        float acc = sum2(acc0) + sum2(acc1);
        acc += __shfl_xor_sync(0xffffffffu, acc, 8);
        acc += __shfl_xor_sync(0xffffffffu, acc, 16);
        if (g == 0) g_buf8a[((size_t)vox << 3) + co] = __float2bfloat16(acc);
    }
}

// conv3/conv4: 8->8.  SRC=0: buf8a->buf8b (RESID: out = x - conv),
// SRC=1: buf8b->buf8a.  co=lane&7, g=lane>>3 covers ci 2g,2g+1.
// W layout [k][ci8][co8]; Wsh[k*32+lane] = pack(W[2g][co], W[2g+1][co]).
template <int SRC, int RESID>
__global__ void __launch_bounds__(256) conv88_kernel(const float* __restrict__ W,
                                                     const float* __restrict__ x, int N) {
    __shared__ u32 Wsh[KK * 32];
    for (int t = threadIdx.x; t < KK * 32; t += 256) {
        int lane = t & 31, k = t >> 5;
        int g = lane >> 3, co = lane & 7;
        const float* wb = W + (size_t)k * 64 + co;
        Wsh[t] = pk(wb[(2 * g) * 8], wb[(2 * g + 1) * 8]);
    }
    __syncthreads();
    const __nv_bfloat16* in = (SRC == 0) ? g_buf8a : g_buf8b;
    __nv_bfloat16* out = (SRC == 0) ? g_buf8b : g_buf8a;
    int lane = threadIdx.x & 31;
    int g = lane >> 3, co = lane & 7;
    int nwarp = gridDim.x * 8;
    for (int vox = blockIdx.x * 8 + (threadIdx.x >> 5); vox < N; vox += nwarp) {
        int m = g_meta[vox];
        int cnt = m & 31, off = m >> 5;
        __nv_bfloat162 accv = bf2(0u);
        for (int j = 0; j < cnt; ++j) {
            int e = __ldg(g_entries + off + j);
            int k = e >> 20, s = e & 0xFFFFF;
            u32 q = __ldg(reinterpret_cast<const u32*>(in + ((size_t)s << 3) + (g << 1)));
            accv = __hfma2(bf2(q), bf2(Wsh[(k << 5) + lane]), accv);
        }
        float acc = sum2(accv);
        acc += __shfl_xor_sync(0xffffffffu, acc, 8);
        acc += __shfl_xor_sync(0xffffffffu, acc, 16);
        if (g == 0) {
            float r = RESID ? (x[((size_t)vox << 3) + co] - acc) : acc;
            out[((size_t)vox << 3) + co] = __float2bfloat16(r);
        }
    }
}

// conv5: g_buf8a(bf16,[N,8]) @ Wu1[27,8,32] -> g_buf32.  lane = co.
// Wu1 layout [k][ci8][co32].
__global__ void __launch_bounds__(256) convE_kernel(const float* __restrict__ W, int N) {
    __shared__ uint2 Wsh[KK * 64];
    for (int t = threadIdx.x; t < KK * 64; t += 256) {
        int lane = t & 31, jp = (t >> 5) & 1, k = t >> 6;
        const float* wb = W + (size_t)k * 256 + lane;
        int c = jp * 4;
        uint2 u;
        u.x = pk(wb[c * 32], wb[(c + 1) * 32]);
        u.y = pk(wb[(c + 2) * 32], wb[(c + 3) * 32]);
        Wsh[t] = u;
    }
    __syncthreads();
    int lane = threadIdx.x & 31;
    int nwarp = gridDim.x * 8;
    for (int vox = blockIdx.x * 8 + (threadIdx.x >> 5); vox < N; vox += nwarp) {
        int m = g_meta[vox];
        int cnt = m & 31, off = m >> 5;
        __nv_bfloat162 acc0 = bf2(0u), acc1 = bf2(0u);
        for (int j = 0; j < cnt; ++j) {
            int e = __ldg(g_entries + off + j);
            int k = e >> 20, s = e & 0xFFFFF;
            uint4 q = __ldg(reinterpret_cast<const uint4*>(g_buf8a + ((size_t)s << 3)));
            const uint2* wk = Wsh + (k << 6) + lane;
            uint2 w0 = wk[0], w1 = wk[32];
            acc0 = __hfma2(bf2(q.x), bf2(w0.x), acc0);
            acc1 = __hfma2(bf2(q.y), bf2(w0.y), acc1);
            acc0 = __hfma2(bf2(q.z), bf2(w1.x), acc0);
            acc1 = __hfma2(bf2(q.w), bf2(w1.y), acc1);
        }
        g_buf32[((size_t)vox << 5) + lane] =
            __float2bfloat16(sum2(acc0) + sum2(acc1));
    }
}

// conv6: g_buf32(bf16,[N,32]) @ Wu2[27,32,32] -> d_out(f32), epilogue adds
// tile(x,4).  lane = co.  Wsh[k*256 + ip*32 + lane] (ip=0..7 covers ci
// 4ip..4ip+3).  Row gathered as 4 uniform LDG.128 into registers.
#define WF_U2 (KK * 8 * 32)  // 6912 uint2 = 55296 B
__global__ void __launch_bounds__(256) convF_kernel(const float* __restrict__ W,
                                                    const float* __restrict__ x,
                                                    float* __restrict__ out, int N) {
    extern __shared__ uint2 Wsh[];
    for (int t = threadIdx.x; t < WF_U2; t += 256) {
        int lane = t & 31, ip = (t >> 5) & 7, k = t >> 8;
        const float* wb = W + (size_t)k * 1024 + lane;
        int c = ip * 4;
        uint2 u;
        u.x = pk(wb[c * 32], wb[(c + 1) * 32]);
        u.y = pk(wb[(c + 2) * 32], wb[(c + 3) * 32]);
        Wsh[t] = u;
    }
    __syncthreads();
    int lane = threadIdx.x & 31;
    int nwarp = gridDim.x * 8;
    for (int vox = blockIdx.x * 8 + (threadIdx.x >> 5); vox < N; vox += nwarp) {
        int m = g_meta[vox];
        int cnt = m & 31, off = m >> 5;
        __nv_bfloat162 acc0 = bf2(0u), acc1 = bf2(0u);
        for (int j = 0; j < cnt; ++j) {
            int e = __ldg(g_entries + off + j);
            int k = e >> 20, s = e & 0xFFFFF;
            const uint4* p = reinterpret_cast<const uint4*>(g_buf32 + ((size_t)s << 5));
            uint4 q0 = __ldg(p), q1 = __ldg(p + 1), q2 = __ldg(p + 2), q3 = __ldg(p + 3);
            const uint2* wk = Wsh + (k << 8) + lane;
#define CF_STEP(IP, VA, VB)                          \
    {                                                \
        uint2 w2 = wk[(IP) << 5];                    \
        acc0 = __hfma2(bf2(VA), bf2(w2.x), acc0);    \
        acc1 = __hfma2(bf2(VB), bf2(w2.y), acc1);    \
    }
            CF_STEP(0, q0.x, q0.y)
            CF_STEP(1, q0.z, q0.w)
            CF_STEP(2, q1.x, q1.y)
            CF_STEP(3, q1.z, q1.w)
            CF_STEP(4, q2.x, q2.y)
            CF_STEP(5, q2.z, q2.w)
            CF_STEP(6, q3.x, q3.y)
            CF_STEP(7, q3.z, q3.w)
#undef CF_STEP
        }
        float acc = sum2(acc0) + sum2(acc1);
        out[((size_t)vox << 5) + lane] = acc + x[((size_t)vox << 3) + (lane & 7)];
    }
}

// ---------------------------------------------------------------------------

extern "C" void kernel_launch(void* const* d_in, const int* in_sizes, int n_in,
                              void* d_out, int out_size) {
    const float* x = (const float*)d_in[0];
    const int* nbr = (const int*)d_in[1];
    const void* mask = d_in[2];
    const float* Wd0 = (const float*)d_in[3];
    const float* Wd1 = (const float*)d_in[4];
    const float* Wd2 = (const float*)d_in[5];
    const float* Wu0 = (const float*)d_in[6];
    const float* Wu1 = (const float*)d_in[7];
    const float* Wu2 = (const float*)d_in[8];
    float* out = (float*)d_out;

    int N = in_sizes[0] / 8;
    if (N > N_MAX) N = N_MAX;
    int nb = (N + 255) / 256;

    probe_mask_kernel<<<1, 256>>>((const unsigned char*)mask);
    count_kernel<<<nb, 256>>>(mask, N);
    scan_blocks_kernel<<<1, 1024>>>(nb);
    fill_kernel<<<nb, 256>>>(mask, nbr, N);
    fold_kernel<<<(KK * 8 * 32 + 255) / 256, 256>>>(Wd0);

    const int LB = 1184;  // 8 persistent blocks/SM on 148 SMs
    convA_kernel<<<LB, 256>>>(x, N);
    convB_kernel<<<LB, 256>>>(Wd1, N);
    conv88_kernel<0, 1><<<LB, 256>>>(Wd2, x, N);  // d3, then r = x - d
    conv88_kernel<1, 0><<<LB, 256>>>(Wu0, x, N);
    convE_kernel<<<LB, 256>>>(Wu1, N);

    const int smF = WF_U2 * sizeof(uint2);  // 54 KB -> 4 blocks/SM
    cudaFuncSetAttribute(convF_kernel, cudaFuncAttributeMaxDynamicSharedMemorySize, smF);
    convF_kernel<<<592, 256, smF>>>(Wu2, x, out, N);
}